// round 8
// baseline (speedup 1.0000x reference)
#include <cuda_runtime.h>
#include <cuda_fp16.h>
#include <cuda_bf16.h>
#include <stdint.h>

// Problem constants: T=4, B=4, N=512, D=512, F=2048, H=8, dh=64
#define ROWS   8192              // T*B*N
#define DMODEL 512
#define FDIM   2048
#define S512   (ROWS*DMODEL/4)   // B*N*D  (per-timestep spatial size)
#define S2048  (ROWS*FDIM/4)     // B*N*F

// ---------------- scratch (allocation-free: __device__ globals) ----------------
__device__ float g_x   [ROWS*DMODEL];      // running residual stream (fp32)
__device__ float g_pre [ROWS*DMODEL];      // pre-activation scratch (D=512)
__device__ float g_pre2[ROWS*FDIM];        // pre-activation scratch (F=2048)
__device__ __half g_as[2*ROWS*DMODEL];     // activation splits (x), 2 fp16 limbs
__device__ __half g_es[2*ROWS*DMODEL];     // activation splits (enc)
__device__ __half g_qb[ROWS*DMODEL];       // q spikes (fp16, exact)
__device__ __half g_kb[ROWS*DMODEL];
__device__ __half g_vb[ROWS*DMODEL];
__device__ __half g_tb[ROWS*DMODEL];       // attn spikes
__device__ __half g_hb[ROWS*FDIM];         // MLP hidden spikes
__device__ __half g_ws[2*FDIM*DMODEL];     // weight splits, transposed [N][K], 2 limbs

// ---------------- split kernels ----------------
// fp32 -> 2 fp16 limbs. x = h + m + r, |r| <= 2^-24 |x|
__global__ void asplit2(const float* __restrict__ X,
                        __half* __restrict__ a0,
                        __half* __restrict__ a1, int n4)
{
    int i = blockIdx.x * blockDim.x + threadIdx.x;
    if (i >= n4) return;
    float4 x = ((const float4*)X)[i];
    float v[4] = {x.x, x.y, x.z, x.w};
    __half h[4], m[4];
    #pragma unroll
    for (int z = 0; z < 4; z++) {
        h[z] = __float2half(v[z]);
        m[z] = __float2half(v[z] - __half2float(h[z]));
    }
    __half2* p0 = (__half2*)(a0 + 4*(size_t)i);
    __half2* p1 = (__half2*)(a1 + 4*(size_t)i);
    p0[0] = __half2(h[0], h[1]); p0[1] = __half2(h[2], h[3]);
    p1[0] = __half2(m[0], m[1]); p1[1] = __half2(m[2], m[3]);
}

// W[K][N] fp32 -> 2 fp16 limbs transposed: wj[N][K]
__global__ void wsplit2(const float* __restrict__ W,
                        __half* __restrict__ w0,
                        __half* __restrict__ w1, int K, int N)
{
    __shared__ float t[32][33];
    const int tid = threadIdx.x;
    const int n0 = blockIdx.x * 32;
    const int k0 = blockIdx.y * 32;
    for (int i = tid; i < 1024; i += 256) {
        int r = i >> 5, c = i & 31;            // r: k, c: n
        t[r][c] = W[(size_t)(k0 + r) * N + n0 + c];
    }
    __syncthreads();
    for (int i = tid; i < 1024; i += 256) {
        int r = i >> 5, c = i & 31;            // r: n, c: k
        float x = t[c][r];
        __half h = __float2half(x);
        __half m = __float2half(x - __half2float(h));
        size_t o = (size_t)(n0 + r) * K + k0 + c;
        w0[o] = h; w1[o] = m;
    }
}

// ---------------- tensor-core GEMM: C = sum_seg A_seg[M,K] @ Wt_seg[N,K]^T + bias ----------------
struct Segs { const __half* a[3]; const __half* w[3]; };

#define SMP 40   // padded smem k-stride (halves): 80B row stride, LDSM conflict-free

__global__ __launch_bounds__(256, 2) void gemm_mma(
    Segs segs, int nseg, const float* __restrict__ bias,
    float* __restrict__ C, int N, int K)
{
    __shared__ __align__(16) __half As[2][128][SMP];
    __shared__ __align__(16) __half Ws[2][128][SMP];

    const int tid  = threadIdx.x;
    const int m0   = blockIdx.y * 128;
    const int n0   = blockIdx.x * 128;
    const int lane = tid & 31;
    const int warp = tid >> 5;
    const int wm   = warp >> 2;   // 0..1 -> 64 rows
    const int wn   = warp & 3;    // 0..3 -> 32 cols
    const int r    = lane >> 2;
    const int q    = lane & 3;

    const int ktiles = K >> 5;
    const int TT = nseg * ktiles;

    const uint32_t asBase = (uint32_t)__cvta_generic_to_shared(&As[0][0][0]);
    const uint32_t wsBase = (uint32_t)__cvta_generic_to_shared(&Ws[0][0][0]);

    // ldmatrix per-lane offsets (halves)
    const int aRow = (lane & 7) + ((lane >> 3) & 1) * 8;  // row within 16-block
    const int aCol = (lane >> 4) * 8;                     // k-half select
    const int bRow = (lane & 7) + (lane >> 4) * 8;        // n-row within 16-block
    const int bCol = ((lane >> 3) & 1) * 8;               // k-half select

    float acc[4][4][4];
    #pragma unroll
    for (int i = 0; i < 4; i++)
        #pragma unroll
        for (int j = 0; j < 4; j++)
            #pragma unroll
            for (int z = 0; z < 4; z++) acc[i][j][z] = 0.f;

    int seg_n = 0, kk_n = 0;

    auto load_tile = [&](int buf) {
        const __half* ap = segs.a[seg_n];
        const __half* wp = segs.w[seg_n];
        #pragma unroll
        for (int u = 0; u < 2; ++u) {
            int c   = tid + (u << 8);
            int row = c >> 2;
            int col = (c & 3) << 3;  // halves (8 per 16B)
            const __half* sa = ap + (size_t)(m0 + row) * K + kk_n + col;
            const __half* sw = wp + (size_t)(n0 + row) * K + kk_n + col;
            uint32_t da = asBase + (uint32_t)(buf * 128 * SMP + row * SMP + col) * 2;
            uint32_t dw = wsBase + (uint32_t)(buf * 128 * SMP + row * SMP + col) * 2;
            asm volatile("cp.async.cg.shared.global [%0], [%1], 16;" :: "r"(da), "l"(sa));
            asm volatile("cp.async.cg.shared.global [%0], [%1], 16;" :: "r"(dw), "l"(sw));
        }
        kk_n += 32;
        if (kk_n == K) { kk_n = 0; seg_n++; }
    };

    load_tile(0);
    asm volatile("cp.async.commit_group;");

    for (int tt = 0; tt < TT; ++tt) {
        const int buf = tt & 1;
        if (tt + 1 < TT) {
            load_tile(buf ^ 1);
            asm volatile("cp.async.commit_group;");
            asm volatile("cp.async.wait_group 1;");
        } else {
            asm volatile("cp.async.wait_group 0;");
        }
        __syncthreads();

        const uint32_t aTile = asBase + (uint32_t)(buf * 128 * SMP) * 2;
        const uint32_t wTile = wsBase + (uint32_t)(buf * 128 * SMP) * 2;

        #pragma unroll
        for (int ko = 0; ko < 32; ko += 16) {
            uint32_t af[4][4], bfr[4][2];
            #pragma unroll
            for (int i = 0; i < 4; i++) {
                uint32_t addr = aTile +
                    (uint32_t)((wm * 64 + i * 16 + aRow) * SMP + ko + aCol) * 2;
                asm volatile(
                    "ldmatrix.sync.aligned.m8n8.x4.shared.b16 {%0,%1,%2,%3}, [%4];"
                    : "=r"(af[i][0]), "=r"(af[i][1]), "=r"(af[i][2]), "=r"(af[i][3])
                    : "r"(addr));
            }
            #pragma unroll
            for (int jj = 0; jj < 2; jj++) {
                uint32_t addr = wTile +
                    (uint32_t)((wn * 32 + jj * 16 + bRow) * SMP + ko + bCol) * 2;
                asm volatile(
                    "ldmatrix.sync.aligned.m8n8.x4.shared.b16 {%0,%1,%2,%3}, [%4];"
                    : "=r"(bfr[2*jj][0]), "=r"(bfr[2*jj][1]),
                      "=r"(bfr[2*jj+1][0]), "=r"(bfr[2*jj+1][1])
                    : "r"(addr));
            }
            #pragma unroll
            for (int i = 0; i < 4; i++)
                #pragma unroll
                for (int j = 0; j < 4; j++)
                    asm volatile(
                        "mma.sync.aligned.m16n8k16.row.col.f32.f16.f16.f32 "
                        "{%0,%1,%2,%3}, {%4,%5,%6,%7}, {%8,%9}, {%0,%1,%2,%3};"
                        : "+f"(acc[i][j][0]), "+f"(acc[i][j][1]),
                          "+f"(acc[i][j][2]), "+f"(acc[i][j][3])
                        : "r"(af[i][0]), "r"(af[i][1]), "r"(af[i][2]), "r"(af[i][3]),
                          "r"(bfr[j][0]), "r"(bfr[j][1]));
        }
        __syncthreads();
    }

    // epilogue: bias add + fp32 store
    #pragma unroll
    for (int i = 0; i < 4; i++) {
        const int R0 = m0 + wm * 64 + i * 16 + r;
        #pragma unroll
        for (int j = 0; j < 4; j++) {
            const int C0 = n0 + wn * 32 + j * 8 + 2 * q;
            const float b0 = bias[C0], b1 = bias[C0 + 1];
            float2 o0, o1;
            o0.x = acc[i][j][0] + b0; o0.y = acc[i][j][1] + b1;
            o1.x = acc[i][j][2] + b0; o1.y = acc[i][j][3] + b1;
            *(float2*)&C[(size_t)R0 * N + C0] = o0;
            *(float2*)&C[(size_t)(R0 + 8) * N + C0] = o1;
        }
    }
}

// ---------------- LIF scan over T=4 ----------------
// pre fp32 [4,S] -> spikes fp16 [4,S]
__global__ void lif4h(const float* __restrict__ pre, __half* __restrict__ out, int S)
{
    const int i = blockIdx.x * blockDim.x + threadIdx.x;
    if (i >= S) return;
    float vmem = 0.f;
    #pragma unroll
    for (int t = 0; t < 4; t++) {
        float u = (vmem + pre[(size_t)t * S + i]) * 0.5f;
        if (u >= 1.0f) { out[(size_t)t * S + i] = __float2half(1.0f); vmem = 0.0f; }
        else           { out[(size_t)t * S + i] = __float2half(0.0f); vmem = u;    }
    }
}

// LIF + residual add into fp32 x
__global__ void lif4_add(const float* __restrict__ pre, float* __restrict__ x, int S)
{
    const int i = blockIdx.x * blockDim.x + threadIdx.x;
    if (i >= S) return;
    float vmem = 0.f;
    #pragma unroll
    for (int t = 0; t < 4; t++) {
        float u = (vmem + pre[(size_t)t * S + i]) * 0.5f;
        if (u >= 1.0f) { x[(size_t)t * S + i] += 1.0f; vmem = 0.0f; }
        else           { vmem = u; }
    }
}

// ---------------- Attention: out = q (kT v) * alpha, binary fp16 spikes ----------------
__device__ __forceinline__ void unp8h(const __half* g, float* dst)
{
    uint4 u = *reinterpret_cast<const uint4*>(g);
    const __half2* p = reinterpret_cast<const __half2*>(&u);
    #pragma unroll
    for (int z = 0; z < 4; z++) {
        float2 f = __half22float2(p[z]);
        dst[2 * z] = f.x; dst[2 * z + 1] = f.y;
    }
}

__global__ __launch_bounds__(256) void attn_kernel(
    const __half* __restrict__ q, const __half* __restrict__ k,
    const __half* __restrict__ v, float* __restrict__ out)
{
    __shared__ float ktv[64][64];
    __shared__ float ks [64][64];
    __shared__ float vs [64][64];

    const int tid     = threadIdx.x;
    const int h       = blockIdx.x & 7;
    const int tb      = blockIdx.x >> 3;
    const int rowbase = tb * 512;
    const int cbase   = h * 64;

    const int d  = tid >> 2;
    const int e0 = (tid & 3) * 16;
    float acc[16];
    #pragma unroll
    for (int j = 0; j < 16; j++) acc[j] = 0.f;

    for (int m0 = 0; m0 < 512; m0 += 64) {
        for (int i = tid; i < 512; i += 256) {
            const int r = i >> 3;
            const int c = (i & 7) * 8;
            const size_t go = (size_t)(rowbase + m0 + r) * 512 + cbase + c;
            unp8h(k + go, &ks[r][c]);
            unp8h(v + go, &vs[r][c]);
        }
        __syncthreads();
        #pragma unroll 4
        for (int mm = 0; mm < 64; mm++) {
            const float kd = ks[mm][d];
            if (kd != 0.f) {
                #pragma unroll
                for (int j = 0; j < 16; j++) acc[j] += vs[mm][e0 + j];
            }
        }
        __syncthreads();
    }
    #pragma unroll
    for (int j = 0; j < 16; j++) ktv[d][e0 + j] = acc[j];
    __syncthreads();

    for (int n0 = 0; n0 < 512; n0 += 64) {
        for (int i = tid; i < 512; i += 256) {
            const int r = i >> 3;
            const int c = (i & 7) * 8;
            unp8h(q + (size_t)(rowbase + n0 + r) * 512 + cbase + c, &ks[r][c]);
        }
        __syncthreads();
        const int rn  = tid >> 2;
        const int ee0 = (tid & 3) * 16;
        float o[16];
        #pragma unroll
        for (int j = 0; j < 16; j++) o[j] = 0.f;
        #pragma unroll 4
        for (int dd = 0; dd < 64; dd++) {
            const float qd = ks[rn][dd];
            if (qd != 0.f) {
                #pragma unroll
                for (int j = 0; j < 16; j++) o[j] += ktv[dd][ee0 + j];
            }
        }
        #pragma unroll
        for (int j = 0; j < 16; j += 4) {
            float4 ov;
            ov.x = o[j + 0] * 0.125f; ov.y = o[j + 1] * 0.125f;
            ov.z = o[j + 2] * 0.125f; ov.w = o[j + 3] * 0.125f;
            *(float4*)&out[(size_t)(rowbase + n0 + rn) * 512 + cbase + ee0 + j] = ov;
        }
        __syncthreads();
    }
}

// ---------------- host-side orchestration ----------------
struct Ptrs {
    float *gx, *gpre, *gpre2;
    __half *as0, *as1, *es0, *es1;
    __half *qb, *kb, *vb, *tb, *hb;
    __half *ws0, *ws1;
};

static void conv_w(const Ptrs& p, const float* W, int K, int N)
{
    wsplit2<<<dim3(N / 32, K / 32), 256>>>(W, p.ws0, p.ws1, K, N);
}

// fp32-input GEMM: 3 products (h,h)(m,h)(h,m)
static void gemmF(const Ptrs& p, const __half* a0, const __half* a1,
                  const float* bias, float* C, int N, int K)
{
    Segs s;
    s.a[0] = a0; s.w[0] = p.ws0;
    s.a[1] = a1; s.w[1] = p.ws0;
    s.a[2] = a0; s.w[2] = p.ws1;
    gemm_mma<<<dim3(N / 128, ROWS / 128), 256>>>(s, 3, bias, C, N, K);
}

// binary-input GEMM: 2 products (s,h)(s,m)
static void gemmB(const Ptrs& p, const __half* a, const float* bias,
                  float* C, int N, int K)
{
    Segs s;
    s.a[0] = a; s.w[0] = p.ws0;
    s.a[1] = a; s.w[1] = p.ws1;
    s.a[2] = a; s.w[2] = p.ws0;
    gemm_mma<<<dim3(N / 128, ROWS / 128), 256>>>(s, 2, bias, C, N, K);
}

static void run_ssa(const Ptrs& p,
                    const __half* q0, const __half* q1,
                    const __half* kv0, const __half* kv1,
                    const float* Wq, const float* bq, const float* Wk, const float* bk,
                    const float* Wv, const float* bv, const float* Wo, const float* bo)
{
    const int lg = S512 / 256;
    conv_w(p, Wq, DMODEL, DMODEL);
    gemmF(p, q0, q1, bq, p.gpre, DMODEL, DMODEL);
    lif4h<<<lg, 256>>>(p.gpre, p.qb, S512);
    conv_w(p, Wk, DMODEL, DMODEL);
    gemmF(p, kv0, kv1, bk, p.gpre, DMODEL, DMODEL);
    lif4h<<<lg, 256>>>(p.gpre, p.kb, S512);
    conv_w(p, Wv, DMODEL, DMODEL);
    gemmF(p, kv0, kv1, bv, p.gpre, DMODEL, DMODEL);
    lif4h<<<lg, 256>>>(p.gpre, p.vb, S512);

    attn_kernel<<<128, 256>>>(p.qb, p.kb, p.vb, p.gpre);
    lif4h<<<lg, 256>>>(p.gpre, p.tb, S512);

    conv_w(p, Wo, DMODEL, DMODEL);
    gemmB(p, p.tb, bo, p.gpre, DMODEL, DMODEL);
    lif4_add<<<lg, 256>>>(p.gpre, p.gx, S512);
}

extern "C" void kernel_launch(void* const* d_in, const int* in_sizes, int n_in,
                              void* d_out, int out_size)
{
    const float* x    = (const float*)d_in[0];
    const float* enc  = (const float*)d_in[1];
    const float* Wq_s = (const float*)d_in[2];  const float* bq_s = (const float*)d_in[3];
    const float* Wk_s = (const float*)d_in[4];  const float* bk_s = (const float*)d_in[5];
    const float* Wv_s = (const float*)d_in[6];  const float* bv_s = (const float*)d_in[7];
    const float* Wo_s = (const float*)d_in[8];  const float* bo_s = (const float*)d_in[9];
    const float* Wq_c = (const float*)d_in[10]; const float* bq_c = (const float*)d_in[11];
    const float* Wk_c = (const float*)d_in[12]; const float* bk_c = (const float*)d_in[13];
    const float* Wv_c = (const float*)d_in[14]; const float* bv_c = (const float*)d_in[15];
    const float* Wo_c = (const float*)d_in[16]; const float* bo_c = (const float*)d_in[17];
    const float* W1   = (const float*)d_in[18]; const float* b1   = (const float*)d_in[19];
    const float* W2   = (const float*)d_in[20]; const float* b2   = (const float*)d_in[21];

    Ptrs p;
    __half *asb, *esb, *wsb;
    cudaGetSymbolAddress((void**)&p.gx,    g_x);
    cudaGetSymbolAddress((void**)&p.gpre,  g_pre);
    cudaGetSymbolAddress((void**)&p.gpre2, g_pre2);
    cudaGetSymbolAddress((void**)&asb,     g_as);
    cudaGetSymbolAddress((void**)&esb,     g_es);
    cudaGetSymbolAddress((void**)&p.qb,    g_qb);
    cudaGetSymbolAddress((void**)&p.kb,    g_kb);
    cudaGetSymbolAddress((void**)&p.vb,    g_vb);
    cudaGetSymbolAddress((void**)&p.tb,    g_tb);
    cudaGetSymbolAddress((void**)&p.hb,    g_hb);
    cudaGetSymbolAddress((void**)&wsb,     g_ws);
    const size_t SD = (size_t)ROWS * DMODEL;
    p.as0 = asb; p.as1 = asb + SD;
    p.es0 = esb; p.es1 = esb + SD;
    const size_t SW = (size_t)FDIM * DMODEL;
    p.ws0 = wsb; p.ws1 = wsb + SW;

    const int n4  = (ROWS * DMODEL) / 4;
    const int lgD = S512 / 256;

    cudaMemcpyAsync(p.gx, x, SD * sizeof(float), cudaMemcpyDeviceToDevice);

    // ---- self-attention block: x = x + ssa(x, x) ----
    asplit2<<<(n4 + 255) / 256, 256>>>(p.gx, p.as0, p.as1, n4);
    run_ssa(p, p.as0, p.as1, p.as0, p.as1,
            Wq_s, bq_s, Wk_s, bk_s, Wv_s, bv_s, Wo_s, bo_s);

    // ---- cross-attention block: x = x + ssa(x, enc) ----
    asplit2<<<(n4 + 255) / 256, 256>>>(p.gx, p.as0, p.as1, n4);
    asplit2<<<(n4 + 255) / 256, 256>>>(enc,  p.es0, p.es1, n4);
    run_ssa(p, p.as0, p.as1, p.es0, p.es1,
            Wq_c, bq_c, Wk_c, bk_c, Wv_c, bv_c, Wo_c, bo_c);

    // ---- MLP block: x = x + lif(lif(x@W1+b1)@W2+b2) ----
    asplit2<<<(n4 + 255) / 256, 256>>>(p.gx, p.as0, p.as1, n4);
    conv_w(p, W1, DMODEL, FDIM);
    gemmF(p, p.as0, p.as1, b1, p.gpre2, FDIM, DMODEL);
    lif4h<<<S2048 / 256, 256>>>(p.gpre2, p.hb, S2048);
    conv_w(p, W2, FDIM, DMODEL);
    gemmB(p, p.hb, b2, p.gpre, DMODEL, FDIM);
    lif4_add<<<lgD, 256>>>(p.gpre, p.gx, S512);

    cudaMemcpyAsync(d_out, p.gx, SD * sizeof(float), cudaMemcpyDeviceToDevice);
}

// round 10
// speedup vs baseline: 1.1570x; 1.1570x over previous
#include <cuda_runtime.h>
#include <cuda_fp16.h>
#include <stdint.h>

// Problem constants: T=4, B=4, N=512, D=512, F=2048, H=8, dh=64
#define ROWS   8192              // T*B*N
#define DMODEL 512
#define FDIM   2048
#define S512   (ROWS*DMODEL/4)   // B*N*D  (per-timestep spatial size)
#define S2048  (ROWS*FDIM/4)     // B*N*F

// ---------------- scratch (allocation-free: __device__ globals) ----------------
__device__ float g_x   [ROWS*DMODEL];      // running residual stream (fp32)
__device__ float g_pre [ROWS*DMODEL];      // pre-activation scratch (D=512)
__device__ float g_pre2[ROWS*FDIM];        // pre-activation scratch (F=2048)
__device__ __half g_as[2*ROWS*DMODEL];     // activation splits (x), 2 fp16 limbs
__device__ __half g_es[2*ROWS*DMODEL];     // activation splits (enc)
__device__ __half g_qb[ROWS*DMODEL];       // q spikes (fp16, exact)
__device__ __half g_kb[ROWS*DMODEL];
__device__ __half g_vb[ROWS*DMODEL];
__device__ __half g_tb[ROWS*DMODEL];       // attn spikes
__device__ __half g_hb[ROWS*FDIM];         // MLP hidden spikes
__device__ __half g_ws[2*FDIM*DMODEL];     // weight splits, transposed [N][K], 2 limbs

// ---------------- small helpers ----------------
__device__ __forceinline__ uint32_t smem_u32(const void* p) {
    return (uint32_t)__cvta_generic_to_shared(p);
}

__device__ __forceinline__ uint32_t elect_one() {
    uint32_t pred;
    asm volatile("{\n\t.reg .pred p;\n\t"
                 "elect.sync _|p, 0xFFFFFFFF;\n\t"
                 "selp.b32 %0, 1, 0, p;\n\t}"
                 : "=r"(pred));
    return pred;
}

__device__ __forceinline__ void mbar_wait(uint32_t addr, uint32_t parity) {
    asm volatile(
        "{\n\t.reg .pred P;\n\t"
        "WL%=:\n\t"
        "mbarrier.try_wait.parity.acquire.cta.shared::cta.b64 P, [%0], %1, 0x989680;\n\t"
        "@P bra WD%=;\n\t"
        "bra WL%=;\n\t"
        "WD%=:\n\t}"
        :: "r"(addr), "r"(parity) : "memory");
}

// SW128 K-major smem descriptor: layout=2, version=1(Blackwell), SBO=64, LBO=1
__device__ __forceinline__ uint64_t mkdesc(uint32_t addr) {
    const uint64_t base = (2ull << 61) | (1ull << 46) | (64ull << 32) | (1ull << 16);
    return base | ((addr >> 4) & 0x3FFF);
}

// idesc for tcgen05 kind::f16: dtype=F32(bit4), atype=btype=f16(0),
// N=128 -> (128/8)<<17, M=128 -> (128/16)<<24
#define IDESC_TC ((1u << 4) | (16u << 17) | (8u << 24))

// ---------------- split / fused elementwise kernels ----------------
// copy x -> gx, and write 2 fp16 limbs of x
__global__ void copy_split(const float* __restrict__ X, float* __restrict__ gx,
                           __half* __restrict__ a0, __half* __restrict__ a1, int n)
{
    int i = blockIdx.x * blockDim.x + threadIdx.x;
    if (i >= n) return;
    float v = X[i];
    gx[i] = v;
    __half h = __float2half(v);
    a0[i] = h;
    a1[i] = __float2half(v - __half2float(h));
}

// fp32 -> 2 fp16 limbs (for enc)
__global__ void asplit2(const float* __restrict__ X,
                        __half* __restrict__ a0,
                        __half* __restrict__ a1, int n)
{
    int i = blockIdx.x * blockDim.x + threadIdx.x;
    if (i >= n) return;
    float v = X[i];
    __half h = __float2half(v);
    a0[i] = h;
    a1[i] = __float2half(v - __half2float(h));
}

// W[K][N] fp32 -> 2 fp16 limbs transposed: wj[N][K]
__global__ void wsplit2(const float* __restrict__ W,
                        __half* __restrict__ w0,
                        __half* __restrict__ w1, int K, int N)
{
    __shared__ float t[32][33];
    const int tid = threadIdx.x;
    const int n0 = blockIdx.x * 32;
    const int k0 = blockIdx.y * 32;
    for (int i = tid; i < 1024; i += 256) {
        int r = i >> 5, c = i & 31;            // r: k, c: n
        t[r][c] = W[(size_t)(k0 + r) * N + n0 + c];
    }
    __syncthreads();
    for (int i = tid; i < 1024; i += 256) {
        int r = i >> 5, c = i & 31;            // r: n, c: k
        float x = t[c][r];
        __half h = __float2half(x);
        __half m = __float2half(x - __half2float(h));
        size_t o = (size_t)(n0 + r) * K + k0 + c;
        w0[o] = h; w1[o] = m;
    }
}

// LIF: pre fp32 [4,S] -> spikes fp16 [4,S]
__global__ void lif4h(const float* __restrict__ pre, __half* __restrict__ out, int S)
{
    const int i = blockIdx.x * blockDim.x + threadIdx.x;
    if (i >= S) return;
    float vmem = 0.f;
    #pragma unroll
    for (int t = 0; t < 4; t++) {
        float u = (vmem + pre[(size_t)t * S + i]) * 0.5f;
        if (u >= 1.0f) { out[(size_t)t * S + i] = __float2half(1.0f); vmem = 0.0f; }
        else           { out[(size_t)t * S + i] = __float2half(0.0f); vmem = u;    }
    }
}

// LIF + residual add into x, and write 2 fp16 limbs of the new x
__global__ void lif4_add_split(const float* __restrict__ pre, float* __restrict__ x,
                               __half* __restrict__ a0, __half* __restrict__ a1, int S)
{
    const int i = blockIdx.x * blockDim.x + threadIdx.x;
    if (i >= S) return;
    float vmem = 0.f;
    #pragma unroll
    for (int t = 0; t < 4; t++) {
        const size_t idx = (size_t)t * S + i;
        float u = (vmem + pre[idx]) * 0.5f;
        float xn = x[idx];
        if (u >= 1.0f) { xn += 1.0f; vmem = 0.0f; }
        else           { vmem = u; }
        x[idx] = xn;
        __half h = __float2half(xn);
        a0[idx] = h;
        a1[idx] = __float2half(xn - __half2float(h));
    }
}

// LIF + residual add, writing final result straight to out (fp32)
__global__ void lif4_add_out(const float* __restrict__ pre, const float* __restrict__ x,
                             float* __restrict__ out, int S)
{
    const int i = blockIdx.x * blockDim.x + threadIdx.x;
    if (i >= S) return;
    float vmem = 0.f;
    #pragma unroll
    for (int t = 0; t < 4; t++) {
        const size_t idx = (size_t)t * S + i;
        float u = (vmem + pre[idx]) * 0.5f;
        float s;
        if (u >= 1.0f) { s = 1.0f; vmem = 0.0f; }
        else           { s = 0.0f; vmem = u; }
        out[idx] = x[idx] + s;
    }
}

// ---------------- unified GEMM: C[M,Ntot] = sum_seg A_seg[M,K] @ Wt_seg[N,K]^T + bias --------
// CTA tile 128x128, 256 threads. tcgen05 path when arch-accelerated features are
// available in this compilation pass; mma.sync 3-stage pipeline otherwise.
struct Segs { const __half* a[3]; const __half* w[3]; };

#define DSM 67584

__global__ __launch_bounds__(256) void gemm_u(
    Segs segs, int nseg, const float* __restrict__ bias,
    float* __restrict__ C, int N, int K)
{
    extern __shared__ char dyn[];
    const int tid  = threadIdx.x;
    const int lane = tid & 31;
    const int warp = tid >> 5;
    const int m0   = blockIdx.y * 128;
    const int n0   = blockIdx.x * 128;

#if defined(__CUDA_ARCH_FEAT_SM103_ALL) || defined(__CUDA_ARCH_FEAT_SM100_ALL)
    // ======================= tcgen05 SS-mode path =======================
    uint32_t rawb = smem_u32(dyn);
    uint32_t base = (rawb + 1023) & ~1023u;
    char* sm = dyn + (base - rawb);
    const uint32_t asb = base;            // A tiles: 2 x 16384B (128 rows x 128B, SW128)
    const uint32_t wsb = base + 32768;    // W tiles: 2 x 16384B
    const uint32_t mb0 = base + 65536;
    const uint32_t mb1 = mb0 + 8;
    uint32_t* tptr = (uint32_t*)(sm + 65600);
    float* bsh = (float*)(sm + 65664);    // 128 f32 bias

    if (warp == 0) {
        asm volatile("tcgen05.alloc.cta_group::1.sync.aligned.shared::cta.b32 [%0], %1;"
                     :: "r"(smem_u32(tptr)), "r"(128) : "memory");
    }
    if (tid == 0) {
        asm volatile("mbarrier.init.shared.b64 [%0], 1;" :: "r"(mb0) : "memory");
        asm volatile("mbarrier.init.shared.b64 [%0], 1;" :: "r"(mb1) : "memory");
    }
    if (tid < 128) bsh[tid] = bias[n0 + tid];
    __syncthreads();
    const uint32_t tmem = *tptr;

    int seg = 0, kk = 0;
    int ph0 = 0, ph1 = 0;
    const int TT = nseg * (K >> 6);

    for (int t = 0; t < TT; ++t) {
        const int buf = t & 1;
        const uint32_t mb = buf ? mb1 : mb0;
        if (t >= 2) {                       // buffer reuse: MMA(t-2) must be done
            if (buf) { mbar_wait(mb, (uint32_t)(ph1 & 1)); ph1++; }
            else     { mbar_wait(mb, (uint32_t)(ph0 & 1)); ph0++; }
        }
        const __half* ap = segs.a[seg];
        const __half* wp = segs.w[seg];
        const uint32_t adst = asb + buf * 16384;
        const uint32_t wdst = wsb + buf * 16384;

        // 128 rows x 128B each operand: 1024 chunks of 16B -> 4 per thread per operand
        #pragma unroll
        for (int i = 0; i < 4; i++) {
            const int idx = tid + (i << 8);
            const int row = idx >> 3;
            const int cb  = (idx & 7) << 4;
            uint32_t off = (uint32_t)(row * 128 + cb);
            off ^= (off >> 3) & 0x70;               // SW128 swizzle
            const __half* sa = ap + (size_t)(m0 + row) * K + kk + (cb >> 1);
            const __half* sw = wp + (size_t)(n0 + row) * K + kk + (cb >> 1);
            asm volatile("cp.async.cg.shared.global [%0], [%1], 16;"
                         :: "r"(adst + off), "l"(sa));
            asm volatile("cp.async.cg.shared.global [%0], [%1], 16;"
                         :: "r"(wdst + off), "l"(sw));
        }
        asm volatile("cp.async.commit_group;");
        asm volatile("cp.async.wait_group 0;");
        __syncthreads();

        if (warp == 4) {
            asm volatile("fence.proxy.async.shared::cta;" ::: "memory");
            if (elect_one()) {
                const uint64_t ad = mkdesc(adst);
                const uint64_t bd = mkdesc(wdst);
                #pragma unroll
                for (int ks = 0; ks < 4; ks++) {    // 4 x K16 covers k-tile 64
                    const uint32_t en = (t > 0 || ks > 0) ? 1u : 0u;
                    asm volatile(
                        "{\n\t.reg .pred p;\n\t"
                        "setp.ne.u32 p, %4, 0;\n\t"
                        "tcgen05.mma.cta_group::1.kind::f16 [%0], %1, %2, %3, {%5,%5,%5,%5}, p;\n\t}"
                        :: "r"(tmem), "l"(ad + ks * 2), "l"(bd + ks * 2),
                           "r"(IDESC_TC), "r"(en), "r"(0u)
                        : "memory");
                }
                asm volatile(
                    "tcgen05.commit.cta_group::1.mbarrier::arrive::one.shared::cluster.b64 [%0];"
                    :: "r"(mb) : "memory");
            }
        }
        kk += 64;
        if (kk == K) { kk = 0; seg++; }
    }

    const int lb = (TT - 1) & 1;
    mbar_wait(lb ? mb1 : mb0, (uint32_t)((lb ? ph1 : ph0) & 1));
    asm volatile("tcgen05.fence::after_thread_sync;" ::: "memory");

    // epilogue: warp w -> rows (w&3)*32, cols (w>>2)*64 (2 chunks of 32)
    const int erow  = m0 + (warp & 3) * 32 + lane;
    const int cbase = (warp >> 2) * 64;
    #pragma unroll
    for (int ch = 0; ch < 2; ch++) {
        const int cb = cbase + ch * 32;
        uint32_t r[32];
        asm volatile(
            "tcgen05.ld.sync.aligned.32x32b.x32.b32 "
            "{%0,%1,%2,%3,%4,%5,%6,%7,%8,%9,%10,%11,%12,%13,%14,%15,"
            "%16,%17,%18,%19,%20,%21,%22,%23,%24,%25,%26,%27,%28,%29,%30,%31}, [%32];"
            : "=r"(r[0]),  "=r"(r[1]),  "=r"(r[2]),  "=r"(r[3]),
              "=r"(r[4]),  "=r"(r[5]),  "=r"(r[6]),  "=r"(r[7]),
              "=r"(r[8]),  "=r"(r[9]),  "=r"(r[10]), "=r"(r[11]),
              "=r"(r[12]), "=r"(r[13]), "=r"(r[14]), "=r"(r[15]),
              "=r"(r[16]), "=r"(r[17]), "=r"(r[18]), "=r"(r[19]),
              "=r"(r[20]), "=r"(r[21]), "=r"(r[22]), "=r"(r[23]),
              "=r"(r[24]), "=r"(r[25]), "=r"(r[26]), "=r"(r[27]),
              "=r"(r[28]), "=r"(r[29]), "=r"(r[30]), "=r"(r[31])
            : "r"(tmem + cb));
        asm volatile("tcgen05.wait::ld.sync.aligned;" ::: "memory");
        #pragma unroll
        for (int j = 0; j < 32; j += 4) {
            float4 o;
            o.x = __uint_as_float(r[j + 0]) + bsh[cb + j + 0];
            o.y = __uint_as_float(r[j + 1]) + bsh[cb + j + 1];
            o.z = __uint_as_float(r[j + 2]) + bsh[cb + j + 2];
            o.w = __uint_as_float(r[j + 3]) + bsh[cb + j + 3];
            *(float4*)&C[(size_t)erow * N + n0 + cb + j] = o;
        }
    }
    asm volatile("tcgen05.fence::before_thread_sync;" ::: "memory");
    __syncthreads();
    if (warp == 0) {
        asm volatile("tcgen05.relinquish_alloc_permit.cta_group::1.sync.aligned;");
        asm volatile("tcgen05.dealloc.cta_group::1.sync.aligned.b32 %0, %1;"
                     :: "r"(tmem), "r"(128));
    }
#else
    // ======================= mma.sync 3-stage fallback =======================
    // smem: 3 stages x (A 128x40h + W 128x40h) = 61440 B
    uint32_t rawb = smem_u32(dyn);
    uint32_t base = (rawb + 15) & ~15u;
    const uint32_t asb = base;
    const uint32_t wsb = base + 30720;

    const int wm = warp >> 2;   // 0..1 -> 64 rows
    const int wn = warp & 3;    // 0..3 -> 32 cols
    const int r  = lane >> 2;
    const int q  = lane & 3;

    const int aRow = (lane & 7) + ((lane >> 3) & 1) * 8;
    const int aCol = (lane >> 4) * 8;
    const int bRow = (lane & 7) + (lane >> 4) * 8;
    const int bCol = ((lane >> 3) & 1) * 8;

    float acc[4][4][4];
    #pragma unroll
    for (int i = 0; i < 4; i++)
        #pragma unroll
        for (int j = 0; j < 4; j++)
            #pragma unroll
            for (int z = 0; z < 4; z++) acc[i][j][z] = 0.f;

    const int ktiles = K >> 5;
    const int TT = nseg * ktiles;

    auto issue = [&](int t) {
        const int buf3 = t % 3;
        const __half* ap = segs.a[t / ktiles];
        const __half* wp = segs.w[t / ktiles];
        const int kk = (t % ktiles) << 5;
        #pragma unroll
        for (int u = 0; u < 2; ++u) {
            const int c   = tid + (u << 8);
            const int row = c >> 2;
            const int col = (c & 3) << 3;  // halves (8 per 16B)
            const __half* sa = ap + (size_t)(m0 + row) * K + kk + col;
            const __half* sw = wp + (size_t)(n0 + row) * K + kk + col;
            const uint32_t da = asb + (uint32_t)(buf3 * 5120 + row * 40 + col) * 2;
            const uint32_t dw = wsb + (uint32_t)(buf3 * 5120 + row * 40 + col) * 2;
            asm volatile("cp.async.cg.shared.global [%0], [%1], 16;" :: "r"(da), "l"(sa));
            asm volatile("cp.async.cg.shared.global [%0], [%1], 16;" :: "r"(dw), "l"(sw));
        }
        asm volatile("cp.async.commit_group;");
    };

    issue(0);
    issue(1);

    for (int tt = 0; tt < TT; ++tt) {
        if (tt == TT - 1) asm volatile("cp.async.wait_group 0;");
        else              asm volatile("cp.async.wait_group 1;");
        __syncthreads();
        if (tt + 2 < TT) issue(tt + 2);

        const int buf3 = tt % 3;
        const uint32_t aT = asb + (uint32_t)(buf3 * 5120) * 2;
        const uint32_t wT = wsb + (uint32_t)(buf3 * 5120) * 2;

        #pragma unroll
        for (int ko = 0; ko < 32; ko += 16) {
            uint32_t af[4][4], bfr[4][2];
            #pragma unroll
            for (int i = 0; i < 4; i++) {
                const uint32_t addr = aT +
                    (uint32_t)((wm * 64 + i * 16 + aRow) * 40 + ko + aCol) * 2;
                asm volatile(
                    "ldmatrix.sync.aligned.m8n8.x4.shared.b16 {%0,%1,%2,%3}, [%4];"
                    : "=r"(af[i][0]), "=r"(af[i][1]), "=r"(af[i][2]), "=r"(af[i][3])
                    : "r"(addr));
            }
            #pragma unroll
            for (int jj = 0; jj < 2; jj++) {
                const uint32_t addr = wT +
                    (uint32_t)((wn * 32 + jj * 16 + bRow) * 40 + ko + bCol) * 2;
                asm volatile(
                    "ldmatrix.sync.aligned.m8n8.x4.shared.b16 {%0,%1,%2,%3}, [%4];"
                    : "=r"(bfr[2*jj][0]), "=r"(bfr[2*jj][1]),
                      "=r"(bfr[2*jj+1][0]), "=r"(bfr[2*jj+1][1])
                    : "r"(addr));
            }
            #pragma unroll
            for (int i = 0; i < 4; i++)
                #pragma unroll
                for (int j = 0; j < 4; j++)
                    asm volatile(
                        "mma.sync.aligned.m16n8k16.row.col.f32.f16.f16.f32 "
                        "{%0,%1,%2,%3}, {%4,%5,%6,%7}, {%8,%9}, {%0,%1,%2,%3};"
                        : "+f"(acc[i][j][0]), "+f"(acc[i][j][1]),
                          "+f"(acc[i][j][2]), "+f"(acc[i][j][3])
                        : "r"(af[i][0]), "r"(af[i][1]), "r"(af[i][2]), "r"(af[i][3]),
                          "r"(bfr[j][0]), "r"(bfr[j][1]));
        }
        __syncthreads();
    }

    // epilogue: bias add + fp32 store
    #pragma unroll
    for (int i = 0; i < 4; i++) {
        const int R0 = m0 + wm * 64 + i * 16 + r;
        #pragma unroll
        for (int j = 0; j < 4; j++) {
            const int C0 = n0 + wn * 32 + j * 8 + 2 * q;
            const float b0 = bias[C0], b1 = bias[C0 + 1];
            float2 o0, o1;
            o0.x = acc[i][j][0] + b0; o0.y = acc[i][j][1] + b1;
            o1.x = acc[i][j][2] + b0; o1.y = acc[i][j][3] + b1;
            *(float2*)&C[(size_t)R0 * N + C0] = o0;
            *(float2*)&C[(size_t)(R0 + 8) * N + C0] = o1;
        }
    }
#endif
}

// ---------------- Attention: out = q (kT v) * alpha, binary fp16 spikes ----------------
__device__ __forceinline__ void unp8h(const __half* g, float* dst)
{
    uint4 u = *reinterpret_cast<const uint4*>(g);
    const __half2* p = reinterpret_cast<const __half2*>(&u);
    #pragma unroll
    for (int z = 0; z < 4; z++) {
        float2 f = __half22float2(p[z]);
        dst[2 * z] = f.x; dst[2 * z + 1] = f.y;
    }
}

__global__ __launch_bounds__(256) void attn_kernel(
    const __half* __restrict__ q, const __half* __restrict__ k,
    const __half* __restrict__ v, float* __restrict__ out)
{
    __shared__ float ktv[64][64];
    __shared__ float ks [64][64];
    __shared__ float vs [64][64];

    const int tid     = threadIdx.x;
    const int h       = blockIdx.x & 7;
    const int tb      = blockIdx.x >> 3;
    const int rowbase = tb * 512;
    const int cbase   = h * 64;

    const int d  = tid >> 2;
    const int e0 = (tid & 3) * 16;
    float acc[16];
    #pragma unroll
    for (int j = 0; j < 16; j++) acc[j] = 0.f;

    for (int m0 = 0; m0 < 512; m0 += 64) {
        for (int i = tid; i < 512; i += 256) {
            const int r = i >> 3;
            const int c = (i & 7) * 8;
            const size_t go = (size_t)(rowbase + m0 + r) * 512 + cbase + c;
            unp8h(k + go, &ks[r][c]);
            unp8h(v + go, &vs[r][c]);
        }
        __syncthreads();
        #pragma unroll 4
        for (int mm = 0; mm < 64; mm++) {
            const float kd = ks[mm][d];
            if (kd != 0.f) {
                #pragma unroll
                for (int j = 0; j < 16; j++) acc[j] += vs[mm][e0 + j];
            }
        }
        __syncthreads();
    }
    #pragma unroll
    for (int j = 0; j < 16; j++) ktv[d][e0 + j] = acc[j];
    __syncthreads();

    for (int n0 = 0; n0 < 512; n0 += 64) {
        for (int i = tid; i < 512; i += 256) {
            const int r = i >> 3;
            const int c = (i & 7) * 8;
            unp8h(q + (size_t)(rowbase + n0 + r) * 512 + cbase + c, &ks[r][c]);
        }
        __syncthreads();
        const int rn  = tid >> 2;
        const int ee0 = (tid & 3) * 16;
        float o[16];
        #pragma unroll
        for (int j = 0; j < 16; j++) o[j] = 0.f;
        #pragma unroll 4
        for (int dd = 0; dd < 64; dd++) {
            const float qd = ks[rn][dd];
            if (qd != 0.f) {
                #pragma unroll
                for (int j = 0; j < 16; j++) o[j] += ktv[dd][ee0 + j];
            }
        }
        #pragma unroll
        for (int j = 0; j < 16; j += 4) {
            float4 ov;
            ov.x = o[j + 0] * 0.125f; ov.y = o[j + 1] * 0.125f;
            ov.z = o[j + 2] * 0.125f; ov.w = o[j + 3] * 0.125f;
            *(float4*)&out[(size_t)(rowbase + n0 + rn) * 512 + cbase + ee0 + j] = ov;
        }
        __syncthreads();
    }
}

// ---------------- host-side orchestration ----------------
struct Ptrs {
    float *gx, *gpre, *gpre2;
    __half *as0, *as1, *es0, *es1;
    __half *qb, *kb, *vb, *tb, *hb;
    __half *ws0, *ws1;
};

static void conv_w(const Ptrs& p, const float* W, int K, int N)
{
    wsplit2<<<dim3(N / 32, K / 32), 256>>>(W, p.ws0, p.ws1, K, N);
}

static void launch_gemm(const Segs& s, int nseg, const float* bias,
                        float* C, int N, int K)
{
    cudaFuncSetAttribute(gemm_u, cudaFuncAttributeMaxDynamicSharedMemorySize, DSM);
    gemm_u<<<dim3(N / 128, ROWS / 128), 256, DSM>>>(s, nseg, bias, C, N, K);
}

// fp32-input GEMM: 3 products (h,h)(m,h)(h,m)
static void gemmF(const Ptrs& p, const __half* a0, const __half* a1,
                  const float* bias, float* C, int N, int K)
{
    Segs s;
    s.a[0] = a0; s.w[0] = p.ws0;
    s.a[1] = a1; s.w[1] = p.ws0;
    s.a[2] = a0; s.w[2] = p.ws1;
    launch_gemm(s, 3, bias, C, N, K);
}

// binary-input GEMM: 2 products (s,h)(s,m)
static void gemmB(const Ptrs& p, const __half* a, const float* bias,
                  float* C, int N, int K)
{
    Segs s;
    s.a[0] = a; s.w[0] = p.ws0;
    s.a[1] = a; s.w[1] = p.ws1;
    s.a[2] = a; s.w[2] = p.ws0;
    launch_gemm(s, 2, bias, C, N, K);
}

// one SSA block; ends with fused residual-LIF + re-split of x
static void run_ssa(const Ptrs& p,
                    const __half* q0, const __half* q1,
                    const __half* kv0, const __half* kv1,
                    const float* Wq, const float* bq, const float* Wk, const float* bk,
                    const float* Wv, const float* bv, const float* Wo, const float* bo)
{
    const int lg = S512 / 256;
    conv_w(p, Wq, DMODEL, DMODEL);
    gemmF(p, q0, q1, bq, p.gpre, DMODEL, DMODEL);
    lif4h<<<lg, 256>>>(p.gpre, p.qb, S512);
    conv_w(p, Wk, DMODEL, DMODEL);
    gemmF(p, kv0, kv1, bk, p.gpre, DMODEL, DMODEL);
    lif4h<<<lg, 256>>>(p.gpre, p.kb, S512);
    conv_w(p, Wv, DMODEL, DMODEL);
    gemmF(p, kv0, kv1, bv, p.gpre, DMODEL, DMODEL);
    lif4h<<<lg, 256>>>(p.gpre, p.vb, S512);

    attn_kernel<<<128, 256>>>(p.qb, p.kb, p.vb, p.gpre);
    lif4h<<<lg, 256>>>(p.gpre, p.tb, S512);

    conv_w(p, Wo, DMODEL, DMODEL);
    gemmB(p, p.tb, bo, p.gpre, DMODEL, DMODEL);
    lif4_add_split<<<lg, 256>>>(p.gpre, p.gx, p.as0, p.as1, S512);
}

extern "C" void kernel_launch(void* const* d_in, const int* in_sizes, int n_in,
                              void* d_out, int out_size)
{
    const float* x    = (const float*)d_in[0];
    const float* enc  = (const float*)d_in[1];
    const float* Wq_s = (const float*)d_in[2];  const float* bq_s = (const float*)d_in[3];
    const float* Wk_s = (const float*)d_in[4];  const float* bk_s = (const float*)d_in[5];
    const float* Wv_s = (const float*)d_in[6];  const float* bv_s = (const float*)d_in[7];
    const float* Wo_s = (const float*)d_in[8];  const float* bo_s = (const float*)d_in[9];
    const float* Wq_c = (const float*)d_in[10]; const float* bq_c = (const float*)d_in[11];
    const float* Wk_c = (const float*)d_in[12]; const float* bk_c = (const float*)d_in[13];
    const float* Wv_c = (const float*)d_in[14]; const float* bv_c = (const float*)d_in[15];
    const float* Wo_c = (const float*)d_in[16]; const float* bo_c = (const float*)d_in[17];
    const float* W1   = (const float*)d_in[18]; const float* b1   = (const float*)d_in[19];
    const float* W2   = (const float*)d_in[20]; const float* b2   = (const float*)d_in[21];

    Ptrs p;
    __half *asb, *esb, *wsb;
    cudaGetSymbolAddress((void**)&p.gx,    g_x);
    cudaGetSymbolAddress((void**)&p.gpre,  g_pre);
    cudaGetSymbolAddress((void**)&p.gpre2, g_pre2);
    cudaGetSymbolAddress((void**)&asb,     g_as);
    cudaGetSymbolAddress((void**)&esb,     g_es);
    cudaGetSymbolAddress((void**)&p.qb,    g_qb);
    cudaGetSymbolAddress((void**)&p.kb,    g_kb);
    cudaGetSymbolAddress((void**)&p.vb,    g_vb);
    cudaGetSymbolAddress((void**)&p.tb,    g_tb);
    cudaGetSymbolAddress((void**)&p.hb,    g_hb);
    cudaGetSymbolAddress((void**)&wsb,     g_ws);
    const size_t SD = (size_t)ROWS * DMODEL;
    p.as0 = asb; p.as1 = asb + SD;
    p.es0 = esb; p.es1 = esb + SD;
    const size_t SW = (size_t)FDIM * DMODEL;
    p.ws0 = wsb; p.ws1 = wsb + SW;

    const int nel = ROWS * DMODEL;
    const int lgD = S512 / 256;

    // x -> gx + limbs in one pass
    copy_split<<<nel / 256, 256>>>(x, p.gx, p.as0, p.as1, nel);

    // ---- self-attention block: x = x + ssa(x, x) ----
    run_ssa(p, p.as0, p.as1, p.as0, p.as1,
            Wq_s, bq_s, Wk_s, bk_s, Wv_s, bv_s, Wo_s, bo_s);

    // ---- cross-attention block: x = x + ssa(x, enc) ----
    asplit2<<<nel / 256, 256>>>(enc, p.es0, p.es1, nel);
    run_ssa(p, p.as0, p.as1, p.es0, p.es1,
            Wq_c, bq_c, Wk_c, bk_c, Wv_c, bv_c, Wo_c, bo_c);

    // ---- MLP block: x = x + lif(lif(x@W1+b1)@W2+b2) ----
    conv_w(p, W1, DMODEL, FDIM);
    gemmF(p, p.as0, p.as1, b1, p.gpre2, FDIM, DMODEL);
    lif4h<<<S2048 / 256, 256>>>(p.gpre2, p.hb, S2048);
    conv_w(p, W2, FDIM, DMODEL);
    gemmB(p, p.hb, b2, p.gpre, DMODEL, FDIM);
    lif4_add_out<<<lgD, 256>>>(p.gpre, p.gx, (float*)d_out, S512);
}